// round 2
// baseline (speedup 1.0000x reference)
#include <cuda_runtime.h>
#include <cuda_bf16.h>
#include <cstdint>

#define DI __device__ __forceinline__

// ---------------- problem sizes ----------------
#define B_  4
#define S_  4096
#define D_  1024
#define M_TOTAL (B_*S_)          // 16384 rows
#define CCH 64                   // scan chunks along S
#define LCH (S_/CCH)             // 64 steps per chunk

// ---------------- scratch (no cudaMalloc allowed) ----------------
__device__ float2 g_cv[(size_t)M_TOTAL * D_];   // (coeff, val) per element: 128 MB
__device__ float  g_p  [B_*CCH*D_];             // chunk coeff products
__device__ float  g_hl [B_*CCH*D_];             // chunk local scan results
__device__ float  g_Hin[B_*CCH*D_];             // carry into each chunk

// ---------------- helpers ----------------
DI uint32_t smem_u32(const void* p) {
    uint32_t a;
    asm("{ .reg .u64 t; cvta.to.shared.u64 t, %1; cvt.u32.u64 %0, t; }" : "=r"(a) : "l"(p));
    return a;
}
DI uint32_t swz(uint32_t o) { return o ^ ((o >> 3) & 0x70); }

DI void ldm_x4(uint32_t* r, uint32_t addr) {
    asm volatile("ldmatrix.sync.aligned.m8n8.x4.shared.b16 {%0,%1,%2,%3}, [%4];"
        : "=r"(r[0]), "=r"(r[1]), "=r"(r[2]), "=r"(r[3]) : "r"(addr));
}
DI void mma_bf16(float* c, const uint32_t* a, uint32_t b0, uint32_t b1) {
    asm volatile(
        "mma.sync.aligned.m16n8k16.row.col.f32.bf16.bf16.f32 "
        "{%0,%1,%2,%3}, {%4,%5,%6,%7}, {%8,%9}, {%0,%1,%2,%3};"
        : "+f"(c[0]), "+f"(c[1]), "+f"(c[2]), "+f"(c[3])
        : "r"(a[0]), "r"(a[1]), "r"(a[2]), "r"(a[3]), "r"(b0), "r"(b1));
}

DI uint32_t pack_bf16(__nv_bfloat16 a, __nv_bfloat16 b) {
    __nv_bfloat162 t; t.x = a; t.y = b;
    return *reinterpret_cast<uint32_t*>(&t);
}
DI void split4(float4 v, uint2& hi, uint2& lo) {
    __nv_bfloat16 h0 = __float2bfloat16(v.x), h1 = __float2bfloat16(v.y);
    __nv_bfloat16 h2 = __float2bfloat16(v.z), h3 = __float2bfloat16(v.w);
    __nv_bfloat16 l0 = __float2bfloat16(v.x - __bfloat162float(h0));
    __nv_bfloat16 l1 = __float2bfloat16(v.y - __bfloat162float(h1));
    __nv_bfloat16 l2 = __float2bfloat16(v.z - __bfloat162float(h2));
    __nv_bfloat16 l3 = __float2bfloat16(v.w - __bfloat162float(h3));
    hi = make_uint2(pack_bf16(h0, h1), pack_bf16(h2, h3));
    lo = make_uint2(pack_bf16(l0, l1), pack_bf16(l2, l3));
}

// ---------------- GEMM + fused elementwise epilogue ----------------
// CTA tile: M=128 rows x 256 mma-cols. B-tile rows interleave hidden/gate:
//   smem B row 2j   = W row (nb*128 + j)        (hidden weights)
//   smem B row 2j+1 = W row (1024 + nb*128 + j) (gate weights)
// so each thread's mma column pair (2*tig, 2*tig+1) = (hidden, gate) for one channel.
// Split bf16 fp32 emulation: C = Ah*Bh + Al*Bh + Ah*Bl (lo*lo dropped, ~2^-18 rel).
#define GT 512
#define KITERS (D_/64)           // 16 K-tiles of 64

#define SM_AHI 0
#define SM_ALO 16384
#define SM_BHI 32768
#define SM_BLO 65536
#define SM_TOTAL 98304

__global__ void __launch_bounds__(GT, 1)
mingru_gemm_kernel(const float* __restrict__ X, const float* __restrict__ W) {
    extern __shared__ char smem[];
    uint32_t sb = smem_u32(smem);
    int tid = threadIdx.x, lane = tid & 31, wid = tid >> 5;
    int wm = wid & 3, wn = wid >> 2;          // 4x4 warp grid
    int nb = blockIdx.x;                      // 8 d-blocks of 128 channels
    int m0 = blockIdx.y * 128;                // 128 row-blocks

    float acc[2][8][4];
    #pragma unroll
    for (int mf = 0; mf < 2; mf++)
        #pragma unroll
        for (int nf = 0; nf < 8; nf++)
            #pragma unroll
            for (int q = 0; q < 4; q++) acc[mf][nf][q] = 0.f;

    int lrow = lane & 15, lk = (lane >> 4) * 16;   // ldmatrix lane addressing

    for (int it = 0; it < KITERS; ++it) {
        int k0 = it * 64;

        // stage gmem -> regs (before barrier, hides latency across sync)
        float4 av[4], bv[8];
        #pragma unroll
        for (int t = 0; t < 4; t++) {
            int idx = tid + t * GT; int r = idx >> 4, c4 = idx & 15;
            av[t] = *(const float4*)(X + (size_t)(m0 + r) * D_ + k0 + c4 * 4);
        }
        #pragma unroll
        for (int t = 0; t < 8; t++) {
            int idx = tid + t * GT; int r = idx >> 4, c4 = idx & 15;
            int j = r >> 1, half = r & 1;
            int wrow = half ? (D_ + nb * 128 + j) : (nb * 128 + j);
            bv[t] = *(const float4*)(W + (size_t)wrow * D_ + k0 + c4 * 4);
        }
        __syncthreads();   // previous tile fully consumed
        #pragma unroll
        for (int t = 0; t < 4; t++) {
            int idx = tid + t * GT; int r = idx >> 4, c4 = idx & 15;
            uint2 hi, lo; split4(av[t], hi, lo);
            uint32_t off = swz((uint32_t)(r * 128 + c4 * 8));
            *(uint2*)(smem + SM_AHI + off) = hi;
            *(uint2*)(smem + SM_ALO + off) = lo;
        }
        #pragma unroll
        for (int t = 0; t < 8; t++) {
            int idx = tid + t * GT; int r = idx >> 4, c4 = idx & 15;
            uint2 hi, lo; split4(bv[t], hi, lo);
            uint32_t off = swz((uint32_t)(r * 128 + c4 * 8));
            *(uint2*)(smem + SM_BHI + off) = hi;
            *(uint2*)(smem + SM_BLO + off) = lo;
        }
        __syncthreads();

        #pragma unroll
        for (int ks = 0; ks < 4; ks++) {
            uint32_t Ah[2][4], Al[2][4], Bf[4][4];
            #pragma unroll
            for (int mf = 0; mf < 2; mf++) {
                uint32_t ro = (uint32_t)((wm * 32 + mf * 16 + lrow) * 128 + ks * 32 + lk);
                ldm_x4(Ah[mf], sb + SM_AHI + swz(ro));
                ldm_x4(Al[mf], sb + SM_ALO + swz(ro));
            }
            #pragma unroll
            for (int p = 0; p < 4; p++) {
                uint32_t ro = (uint32_t)((wn * 64 + p * 16 + lrow) * 128 + ks * 32 + lk);
                ldm_x4(Bf[p], sb + SM_BHI + swz(ro));
            }
            #pragma unroll
            for (int mf = 0; mf < 2; mf++)
                #pragma unroll
                for (int p = 0; p < 4; p++) {
                    mma_bf16(acc[mf][2 * p],     Ah[mf], Bf[p][0], Bf[p][2]);
                    mma_bf16(acc[mf][2 * p + 1], Ah[mf], Bf[p][1], Bf[p][3]);
                }
            #pragma unroll
            for (int mf = 0; mf < 2; mf++)
                #pragma unroll
                for (int p = 0; p < 4; p++) {
                    mma_bf16(acc[mf][2 * p],     Al[mf], Bf[p][0], Bf[p][2]);
                    mma_bf16(acc[mf][2 * p + 1], Al[mf], Bf[p][1], Bf[p][3]);
                }
            #pragma unroll
            for (int p = 0; p < 4; p++) {      // reload as B-lo (reuse regs)
                uint32_t ro = (uint32_t)((wn * 64 + p * 16 + lrow) * 128 + ks * 32 + lk);
                ldm_x4(Bf[p], sb + SM_BLO + swz(ro));
            }
            #pragma unroll
            for (int mf = 0; mf < 2; mf++)
                #pragma unroll
                for (int p = 0; p < 4; p++) {
                    mma_bf16(acc[mf][2 * p],     Ah[mf], Bf[p][0], Bf[p][2]);
                    mma_bf16(acc[mf][2 * p + 1], Ah[mf], Bf[p][1], Bf[p][3]);
                }
        }
    }

    // ---- epilogue: (hidden, gate) pairs live in (c0,c1) / (c2,c3) ----
    int gid = lane >> 2, tig = lane & 3;
    #pragma unroll
    for (int mf = 0; mf < 2; mf++) {
        int r0 = m0 + wm * 32 + mf * 16 + gid;
        #pragma unroll
        for (int nf = 0; nf < 8; nf++) {
            int ch = nb * 128 + wn * 32 + nf * 4 + tig;
            #pragma unroll
            for (int h = 0; h < 2; h++) {
                float hid = acc[mf][nf][2 * h];
                float gat = acc[mf][nf][2 * h + 1];
                float eg  = __expf(-gat);
                float z   = 1.0f / (1.0f + eg);          // sigmoid(gate)
                float cf  = eg * z;                      // 1 - z
                float gg  = (hid >= 0.f) ? (hid + 0.5f)
                                         : (1.0f / (1.0f + __expf(-hid)));
                g_cv[(size_t)(r0 + h * 8) * D_ + ch] = make_float2(cf, z * gg);
            }
        }
    }
}

// ---------------- chunked linear-space scan ----------------
__global__ void __launch_bounds__(256) scan_pass1() {
    int g = blockIdx.x * 256 + threadIdx.x;        // 131072 threads
    int d2 = g & 511; int c = (g >> 9) & 63; int b = g >> 15;
    const float4* ptr = (const float4*)g_cv + (size_t)(b * S_ + c * LCH) * (D_ / 2) + d2;
    float p0 = 1.f, p1 = 1.f, h0 = 0.f, h1 = 0.f;
    #pragma unroll 4
    for (int i = 0; i < LCH; i++) {
        float4 q = ptr[(size_t)i * (D_ / 2)];
        h0 = fmaf(q.x, h0, q.y); p0 *= q.x;
        h1 = fmaf(q.z, h1, q.w); p1 *= q.z;
    }
    int idx = (b * CCH + c) * D_ + d2 * 2;
    *(float2*)(g_p  + idx) = make_float2(p0, p1);
    *(float2*)(g_hl + idx) = make_float2(h0, h1);
}

__global__ void __launch_bounds__(256) scan_pass2() {
    int t = blockIdx.x * 256 + threadIdx.x;        // 4096 threads
    int d = t & (D_ - 1), b = t >> 10;
    float H = 0.f;
    for (int c = 0; c < CCH; c++) {
        int idx = (b * CCH + c) * D_ + d;
        g_Hin[idx] = H;
        H = fmaf(g_p[idx], H, g_hl[idx]);
    }
}

__global__ void __launch_bounds__(256) scan_pass3(float* __restrict__ out) {
    int g = blockIdx.x * 256 + threadIdx.x;
    int d2 = g & 511; int c = (g >> 9) & 63; int b = g >> 15;
    float2 Hi = *(float2*)(g_Hin + (b * CCH + c) * D_ + d2 * 2);
    float h0 = Hi.x, h1 = Hi.y;
    const float4* ptr = (const float4*)g_cv + (size_t)(b * S_ + c * LCH) * (D_ / 2) + d2;
    float* ob = out + (size_t)(b * S_ + c * LCH) * D_ + d2 * 2;
    #pragma unroll 4
    for (int i = 0; i < LCH; i++) {
        float4 q = ptr[(size_t)i * (D_ / 2)];
        h0 = fmaf(q.x, h0, q.y);
        h1 = fmaf(q.z, h1, q.w);
        *(float2*)(ob + (size_t)i * D_) = make_float2(h0, h1);
    }
}

// ---------------- launch ----------------
extern "C" void kernel_launch(void* const* d_in, const int* in_sizes, int n_in,
                              void* d_out, int out_size) {
    const float* x = (const float*)d_in[0];
    const float* w = (const float*)d_in[1];
    if (n_in >= 2 && in_sizes[0] == 2 * D_ * D_) {   // W first? swap
        x = (const float*)d_in[1];
        w = (const float*)d_in[0];
    }
    static bool attr_done = false;
    if (!attr_done) {
        cudaFuncSetAttribute(mingru_gemm_kernel,
                             cudaFuncAttributeMaxDynamicSharedMemorySize, SM_TOTAL);
        attr_done = true;
    }
    dim3 grid(8, M_TOTAL / 128);                     // (8, 128)
    mingru_gemm_kernel<<<grid, GT, SM_TOTAL>>>(x, w);
    scan_pass1<<<(B_ * (D_ / 2) * CCH) / 256, 256>>>();
    scan_pass2<<<(B_ * D_) / 256, 256>>>();
    scan_pass3<<<(B_ * (D_ / 2) * CCH) / 256, 256>>>((float*)d_out);
}

// round 3
// speedup vs baseline: 1.2381x; 1.2381x over previous
#include <cuda_runtime.h>
#include <cuda_bf16.h>
#include <cstdint>

#define DI __device__ __forceinline__

// ---------------- problem sizes ----------------
#define B_  4
#define S_  4096
#define D_  1024
#define M_TOTAL (B_*S_)          // 16384 rows
#define CCH 64                   // scan chunks along S
#define LCH (S_/CCH)             // 64 steps per chunk

// ---------------- scratch (no cudaMalloc allowed) ----------------
__device__ float2 g_cv[(size_t)M_TOTAL * D_];     // (coeff, val): 128 MB
__device__ float  g_p  [B_*CCH*D_];
__device__ float  g_hl [B_*CCH*D_];
__device__ float  g_Hin[B_*CCH*D_];
__device__ uint2  g_xhi[(size_t)M_TOTAL * D_ / 4];   // bf16 x4 per uint2: 32 MB
__device__ uint2  g_xlo[(size_t)M_TOTAL * D_ / 4];
__device__ uint2  g_whi[(size_t)2 * D_ * D_ / 4];    // interleaved layout: 4 MB
__device__ uint2  g_wlo[(size_t)2 * D_ * D_ / 4];

// ---------------- helpers ----------------
DI uint32_t smem_u32(const void* p) {
    uint32_t a;
    asm("{ .reg .u64 t; cvta.to.shared.u64 t, %1; cvt.u32.u64 %0, t; }" : "=r"(a) : "l"(p));
    return a;
}
DI uint32_t swz(uint32_t o) { return o ^ ((o >> 3) & 0x70); }

DI void ldm_x4(uint32_t* r, uint32_t addr) {
    asm volatile("ldmatrix.sync.aligned.m8n8.x4.shared.b16 {%0,%1,%2,%3}, [%4];"
        : "=r"(r[0]), "=r"(r[1]), "=r"(r[2]), "=r"(r[3]) : "r"(addr));
}
DI void mma_bf16(float* c, const uint32_t* a, uint32_t b0, uint32_t b1) {
    asm volatile(
        "mma.sync.aligned.m16n8k16.row.col.f32.bf16.bf16.f32 "
        "{%0,%1,%2,%3}, {%4,%5,%6,%7}, {%8,%9}, {%0,%1,%2,%3};"
        : "+f"(c[0]), "+f"(c[1]), "+f"(c[2]), "+f"(c[3])
        : "r"(a[0]), "r"(a[1]), "r"(a[2]), "r"(a[3]), "r"(b0), "r"(b1));
}
DI void cp16(uint32_t saddr, const void* g) {
    asm volatile("cp.async.cg.shared.global [%0], [%1], 16;" :: "r"(saddr), "l"(g) : "memory");
}
DI void cp_commit() { asm volatile("cp.async.commit_group;" ::: "memory"); }
DI void cp_wait1()  { asm volatile("cp.async.wait_group 1;" ::: "memory"); }
DI void cp_wait0()  { asm volatile("cp.async.wait_group 0;" ::: "memory"); }

DI uint32_t pack_bf16(__nv_bfloat16 a, __nv_bfloat16 b) {
    __nv_bfloat162 t; t.x = a; t.y = b;
    return *reinterpret_cast<uint32_t*>(&t);
}
DI void split4(float4 v, uint2& hi, uint2& lo) {
    __nv_bfloat16 h0 = __float2bfloat16(v.x), h1 = __float2bfloat16(v.y);
    __nv_bfloat16 h2 = __float2bfloat16(v.z), h3 = __float2bfloat16(v.w);
    __nv_bfloat16 l0 = __float2bfloat16(v.x - __bfloat162float(h0));
    __nv_bfloat16 l1 = __float2bfloat16(v.y - __bfloat162float(h1));
    __nv_bfloat16 l2 = __float2bfloat16(v.z - __bfloat162float(h2));
    __nv_bfloat16 l3 = __float2bfloat16(v.w - __bfloat162float(h3));
    hi = make_uint2(pack_bf16(h0, h1), pack_bf16(h2, h3));
    lo = make_uint2(pack_bf16(l0, l1), pack_bf16(l2, l3));
}

// ---------------- precompute: fp32 -> split bf16 ----------------
__global__ void __launch_bounds__(256) prep_x(const float* __restrict__ X) {
    int g = blockIdx.x * 256 + threadIdx.x;            // 4,194,304 float4s
    float4 v = ((const float4*)X)[g];
    uint2 hi, lo; split4(v, hi, lo);
    g_xhi[g] = hi; g_xlo[g] = lo;
}
// W rows permuted to interleaved B layout: channel c -> row 2c (hidden), 2c+1 (gate)
__global__ void __launch_bounds__(256) prep_w(const float* __restrict__ W) {
    int g = blockIdx.x * 256 + threadIdx.x;            // 524,288 float4s
    int sr = g >> 8, c4 = g & 255;
    int c = sr & (D_ - 1), half = sr >> 10;
    int ir = 2 * c + half;
    float4 v = ((const float4*)W)[g];
    uint2 hi, lo; split4(v, hi, lo);
    g_whi[ir * 256 + c4] = hi; g_wlo[ir * 256 + c4] = lo;
}

// ---------------- GEMM + fused elementwise epilogue ----------------
// CTA tile 128(m) x 256(mma-n) x 64(k); B rows interleave hidden/gate so each
// thread's mma column pair (2*tig, 2*tig+1) = (hidden, gate) for one channel.
// Split bf16: C = Ah*Bh + Al*Bh + Ah*Bl. cp.async double-buffered.
#define GT 512
#define KITERS (D_/64)           // 16

#define ST_AHI 0
#define ST_ALO 16384
#define ST_BHI 32768
#define ST_BLO 65536
#define STAGE  98304
#define SM_TOTAL (2*STAGE)       // 192 KB

__global__ void __launch_bounds__(GT, 1)
mingru_gemm_kernel() {
    extern __shared__ char smem[];
    uint32_t sb = smem_u32(smem);
    int tid = threadIdx.x, lane = tid & 31, wid = tid >> 5;
    int wm = wid & 3, wn = wid >> 2;          // 4x4 warp grid
    int nb = blockIdx.x;                      // 8 d-blocks of 128 channels
    int m0 = blockIdx.y * 128;                // 128 row-blocks

    // chunk indices for this thread's cp.async slice
    int cr = tid >> 3, cc = tid & 7;          // A: rows 0..63 (x2), B: rows 0..63 (x4)

    const char* xh = (const char*)g_xhi;
    const char* xl = (const char*)g_xlo;
    const char* wh = (const char*)g_whi;
    const char* wl = (const char*)g_wlo;

    float acc[2][8][4];
    #pragma unroll
    for (int mf = 0; mf < 2; mf++)
        #pragma unroll
        for (int nf = 0; nf < 8; nf++)
            #pragma unroll
            for (int q = 0; q < 4; q++) acc[mf][nf][q] = 0.f;

    int lrow = lane & 15, lk = (lane >> 4) * 16;

    // ---- issue loads for one K-tile into stage st ----
    auto issue = [&](int it, int st) {
        uint32_t base = sb + (uint32_t)(st * STAGE);
        size_t k0b = (size_t)it * 128;                 // 64 bf16 = 128 bytes
        #pragma unroll
        for (int t = 0; t < 2; t++) {
            int r = cr + t * 64;
            size_t go = (size_t)(m0 + r) * 2048 + k0b + cc * 16;
            uint32_t so = swz((uint32_t)(r * 128 + cc * 16));
            cp16(base + ST_AHI + so, xh + go);
            cp16(base + ST_ALO + so, xl + go);
        }
        #pragma unroll
        for (int t = 0; t < 4; t++) {
            int r = cr + t * 64;
            size_t go = (size_t)(nb * 256 + r) * 2048 + k0b + cc * 16;
            uint32_t so = swz((uint32_t)(r * 128 + cc * 16));
            cp16(base + ST_BHI + so, wh + go);
            cp16(base + ST_BLO + so, wl + go);
        }
        cp_commit();
    };

    issue(0, 0);

    for (int it = 0; it < KITERS; ++it) {
        int s = it & 1;
        if (it + 1 < KITERS) issue(it + 1, s ^ 1);
        if (it + 1 < KITERS) cp_wait1(); else cp_wait0();
        __syncthreads();

        uint32_t base = sb + (uint32_t)(s * STAGE);
        #pragma unroll
        for (int ks = 0; ks < 4; ks++) {
            uint32_t Ah[2][4], Al[2][4], Bf[4][4];
            #pragma unroll
            for (int mf = 0; mf < 2; mf++) {
                uint32_t ro = (uint32_t)((wm * 32 + mf * 16 + lrow) * 128 + ks * 32 + lk);
                ldm_x4(Ah[mf], base + ST_AHI + swz(ro));
                ldm_x4(Al[mf], base + ST_ALO + swz(ro));
            }
            #pragma unroll
            for (int p = 0; p < 4; p++) {
                uint32_t ro = (uint32_t)((wn * 64 + p * 16 + lrow) * 128 + ks * 32 + lk);
                ldm_x4(Bf[p], base + ST_BHI + swz(ro));
            }
            #pragma unroll
            for (int mf = 0; mf < 2; mf++)
                #pragma unroll
                for (int p = 0; p < 4; p++) {
                    mma_bf16(acc[mf][2 * p],     Ah[mf], Bf[p][0], Bf[p][2]);
                    mma_bf16(acc[mf][2 * p + 1], Ah[mf], Bf[p][1], Bf[p][3]);
                }
            #pragma unroll
            for (int mf = 0; mf < 2; mf++)
                #pragma unroll
                for (int p = 0; p < 4; p++) {
                    mma_bf16(acc[mf][2 * p],     Al[mf], Bf[p][0], Bf[p][2]);
                    mma_bf16(acc[mf][2 * p + 1], Al[mf], Bf[p][1], Bf[p][3]);
                }
            #pragma unroll
            for (int p = 0; p < 4; p++) {
                uint32_t ro = (uint32_t)((wn * 64 + p * 16 + lrow) * 128 + ks * 32 + lk);
                ldm_x4(Bf[p], base + ST_BLO + swz(ro));
            }
            #pragma unroll
            for (int mf = 0; mf < 2; mf++)
                #pragma unroll
                for (int p = 0; p < 4; p++) {
                    mma_bf16(acc[mf][2 * p],     Ah[mf], Bf[p][0], Bf[p][2]);
                    mma_bf16(acc[mf][2 * p + 1], Ah[mf], Bf[p][1], Bf[p][3]);
                }
        }
        __syncthreads();   // stage s fully consumed; safe to overwrite at it+2
    }

    // ---- epilogue: (hidden, gate) pairs -> (coeff, val) in registers ----
    int gid = lane >> 2, tig = lane & 3;
    #pragma unroll
    for (int mf = 0; mf < 2; mf++) {
        int r0 = m0 + wm * 32 + mf * 16 + gid;
        #pragma unroll
        for (int nf = 0; nf < 8; nf++) {
            int ch = nb * 128 + wn * 32 + nf * 4 + tig;
            #pragma unroll
            for (int h = 0; h < 2; h++) {
                float hid = acc[mf][nf][2 * h];
                float gat = acc[mf][nf][2 * h + 1];
                float eg  = __expf(-gat);
                float z   = 1.0f / (1.0f + eg);          // sigmoid(gate)
                float cf  = eg * z;                      // 1 - z
                float gg  = (hid >= 0.f) ? (hid + 0.5f)
                                         : (1.0f / (1.0f + __expf(-hid)));
                g_cv[(size_t)(r0 + h * 8) * D_ + ch] = make_float2(cf, z * gg);
            }
        }
    }
}

// ---------------- chunked linear-space scan ----------------
__global__ void __launch_bounds__(256) scan_pass1() {
    int g = blockIdx.x * 256 + threadIdx.x;
    int d2 = g & 511; int c = (g >> 9) & 63; int b = g >> 15;
    const float4* ptr = (const float4*)g_cv + (size_t)(b * S_ + c * LCH) * (D_ / 2) + d2;
    float p0 = 1.f, p1 = 1.f, h0 = 0.f, h1 = 0.f;
    #pragma unroll 4
    for (int i = 0; i < LCH; i++) {
        float4 q = ptr[(size_t)i * (D_ / 2)];
        h0 = fmaf(q.x, h0, q.y); p0 *= q.x;
        h1 = fmaf(q.z, h1, q.w); p1 *= q.z;
    }
    int idx = (b * CCH + c) * D_ + d2 * 2;
    *(float2*)(g_p  + idx) = make_float2(p0, p1);
    *(float2*)(g_hl + idx) = make_float2(h0, h1);
}

__global__ void __launch_bounds__(256) scan_pass2() {
    int t = blockIdx.x * 256 + threadIdx.x;
    int d = t & (D_ - 1), b = t >> 10;
    float H = 0.f;
    for (int c = 0; c < CCH; c++) {
        int idx = (b * CCH + c) * D_ + d;
        g_Hin[idx] = H;
        H = fmaf(g_p[idx], H, g_hl[idx]);
    }
}

__global__ void __launch_bounds__(256) scan_pass3(float* __restrict__ out) {
    int g = blockIdx.x * 256 + threadIdx.x;
    int d2 = g & 511; int c = (g >> 9) & 63; int b = g >> 15;
    float2 Hi = *(float2*)(g_Hin + (b * CCH + c) * D_ + d2 * 2);
    float h0 = Hi.x, h1 = Hi.y;
    const float4* ptr = (const float4*)g_cv + (size_t)(b * S_ + c * LCH) * (D_ / 2) + d2;
    float* ob = out + (size_t)(b * S_ + c * LCH) * D_ + d2 * 2;
    #pragma unroll 4
    for (int i = 0; i < LCH; i++) {
        float4 q = ptr[(size_t)i * (D_ / 2)];
        h0 = fmaf(q.x, h0, q.y);
        h1 = fmaf(q.z, h1, q.w);
        *(float2*)(ob + (size_t)i * D_) = make_float2(h0, h1);
    }
}

// ---------------- launch ----------------
extern "C" void kernel_launch(void* const* d_in, const int* in_sizes, int n_in,
                              void* d_out, int out_size) {
    const float* x = (const float*)d_in[0];
    const float* w = (const float*)d_in[1];
    if (n_in >= 2 && in_sizes[0] == 2 * D_ * D_) {
        x = (const float*)d_in[1];
        w = (const float*)d_in[0];
    }
    static bool attr_done = false;
    if (!attr_done) {
        cudaFuncSetAttribute(mingru_gemm_kernel,
                             cudaFuncAttributeMaxDynamicSharedMemorySize, SM_TOTAL);
        attr_done = true;
    }
    prep_x<<<(M_TOTAL * D_ / 4) / 256, 256>>>(x);
    prep_w<<<(2 * D_ * D_ / 4) / 256, 256>>>(w);
    dim3 grid(8, M_TOTAL / 128);
    mingru_gemm_kernel<<<grid, GT, SM_TOTAL>>>();
    scan_pass1<<<(B_ * (D_ / 2) * CCH) / 256, 256>>>();
    scan_pass2<<<(B_ * D_) / 256, 256>>>();
    scan_pass3<<<(B_ * (D_ / 2) * CCH) / 256, 256>>>((float*)d_out);
}